// round 11
// baseline (speedup 1.0000x reference)
#include <cuda_runtime.h>
#include <cstdint>

#define BATCH 2
#define SEQ   2048
#define DM    768
#define NH    12
#define DK    64
#define MROWS (BATCH*SEQ)

// Scratch (allocation-free rule: __device__ globals)
__device__ uint16_t g_xh[MROWS*DM],  g_xl[MROWS*DM];   // x bf16 hi/lo
__device__ uint16_t g_qh[MROWS*DM],  g_ql[MROWS*DM];   // Q (scaled) hi/lo
__device__ uint16_t g_kh[MROWS*DM],  g_kl[MROWS*DM];   // K hi/lo
__device__ uint16_t g_vth[MROWS*DM], g_vtl[MROWS*DM];  // V^T hi/lo [(b,h,dl)][token]
__device__ uint16_t g_ah[MROWS*DM],  g_al[MROWS*DM];   // attention out hi/lo
__device__ uint16_t g_wqh[DM*DM], g_wql[DM*DM];
__device__ uint16_t g_wkh[DM*DM], g_wkl[DM*DM];
__device__ uint16_t g_wvh[DM*DM], g_wvl[DM*DM];
__device__ uint16_t g_woh[DM*DM], g_wol[DM*DM];

// ============================================================================
// helpers
// ============================================================================
__device__ __forceinline__ uint32_t smem_u32(const void* p) {
    uint32_t a;
    asm("{ .reg .u64 t; cvta.to.shared.u64 t, %1; cvt.u32.u64 %0, t; }" : "=r"(a) : "l"(p));
    return a;
}
__device__ __forceinline__ uint32_t bfpack(float x, float y) {
    uint32_t r;
    asm("cvt.rn.bf16x2.f32 %0, %1, %2;" : "=r"(r) : "f"(y), "f"(x));
    return r;
}
__device__ __forceinline__ float lo_of(uint32_t p)  { return __uint_as_float(p << 16); }
__device__ __forceinline__ float hi_of(uint32_t p)  { return __uint_as_float(p & 0xffff0000u); }
__device__ __forceinline__ uint16_t bf1(float x) {
    uint16_t u; asm("cvt.rn.bf16.f32 %0, %1;" : "=h"(u) : "f"(x)); return u;
}
__device__ __forceinline__ float bf1v(uint16_t u) { return __uint_as_float(((uint32_t)u) << 16); }

__device__ __forceinline__ void mma16816(float* c, const uint32_t* a, const uint32_t* b) {
    asm volatile(
        "mma.sync.aligned.m16n8k16.row.col.f32.bf16.bf16.f32 "
        "{%0,%1,%2,%3}, {%4,%5,%6,%7}, {%8,%9}, {%0,%1,%2,%3};"
        : "+f"(c[0]), "+f"(c[1]), "+f"(c[2]), "+f"(c[3])
        : "r"(a[0]), "r"(a[1]), "r"(a[2]), "r"(a[3]), "r"(b[0]), "r"(b[1]));
}
__device__ __forceinline__ void ldsm4(uint32_t* r, uint32_t addr) {
    asm volatile("ldmatrix.sync.aligned.m8n8.x4.shared.b16 {%0,%1,%2,%3}, [%4];"
        : "=r"(r[0]), "=r"(r[1]), "=r"(r[2]), "=r"(r[3]) : "r"(addr));
}
#define CP16(dst, src) asm volatile("cp.async.ca.shared.global [%0], [%1], 16;" :: "r"(dst), "l"(src))
#define CP_COMMIT()    asm volatile("cp.async.commit_group;" ::: "memory")
#define CP_WAIT0()     asm volatile("cp.async.wait_group 0;" ::: "memory")

// ============================================================================
// Elementwise fp32 -> bf16 hi/lo split
// ============================================================================
__global__ __launch_bounds__(256) void conv_split(const float* __restrict__ src,
                                                  uint16_t* __restrict__ dh,
                                                  uint16_t* __restrict__ dl, int n4)
{
    int i = blockIdx.x * blockDim.x + threadIdx.x;
    if (i < n4) {
        float4 v = ((const float4*)src)[i];
        uint32_t h0 = bfpack(v.x, v.y), h1 = bfpack(v.z, v.w);
        ((uint2*)dh)[i] = make_uint2(h0, h1);
        ((uint2*)dl)[i] = make_uint2(bfpack(v.x - lo_of(h0), v.y - hi_of(h0)),
                                     bfpack(v.z - lo_of(h1), v.w - hi_of(h1)));
    }
}

// ============================================================================
// GEMM core on pre-split bf16 inputs: cp.async double-buffered, LDSM, 3x mma.
// ============================================================================
#define SROW 20                        // smem row stride (u32): 16 data + 4 pad
#define GST_U32 (128*SROW)             // 2560 words per array
#define GSTAGE_U32 (4*GST_U32)         // 10240 words per stage
#define G_SMEM (2*GSTAGE_U32*4)        // 81920 B

__device__ __forceinline__ void gemm_core_bf(const uint16_t* __restrict__ Agh,
                                             const uint16_t* __restrict__ Agl,
                                             const uint16_t* __restrict__ Bgh,
                                             const uint16_t* __restrict__ Bgl,
                                             uint32_t smb, int m0, int n0,
                                             int tid, float c[4][4][4])
{
    const int warp = tid >> 5, lane = tid & 31;
    const int wm = warp >> 2, wn = warp & 3;
    const int a_row = lane & 15,                  a_hk = (lane >> 4) * 4;
    const int b_row = ((lane >> 4) << 3) + (lane & 7), b_hk = ((lane >> 3) & 1) * 4;

    auto pre = [&](int kc, int stg) {
#pragma unroll
        for (int u = 0; u < 8; u++) {
            int idx = tid + u * 256;
            int arr = idx >> 9, row = (idx >> 2) & 127, ch = idx & 3;
            const uint16_t* src;
            if      (arr == 0) src = Agh + (long)(m0 + row) * DM + kc * 32 + ch * 8;
            else if (arr == 1) src = Agl + (long)(m0 + row) * DM + kc * 32 + ch * 8;
            else if (arr == 2) src = Bgh + (long)(n0 + row) * DM + kc * 32 + ch * 8;
            else               src = Bgl + (long)(n0 + row) * DM + kc * 32 + ch * 8;
            uint32_t dst = smb + (uint32_t)((stg * 4 + arr) * GST_U32 + row * SROW + ch * 4) * 4;
            CP16(dst, src);
        }
        CP_COMMIT();
    };

    pre(0, 0);

    for (int kc = 0; kc < DM / 32; kc++) {
        const int stg = kc & 1;
        CP_WAIT0();
        __syncthreads();
        if (kc + 1 < DM / 32) pre(kc + 1, stg ^ 1);

        const uint32_t sAh = smb + (uint32_t)(stg * GSTAGE_U32) * 4;
        const uint32_t sAl = sAh + GST_U32 * 4;
        const uint32_t sBh = sAh + 2 * GST_U32 * 4;
        const uint32_t sBl = sAh + 3 * GST_U32 * 4;

#pragma unroll
        for (int ks = 0; ks < 2; ks++) {
            uint32_t bh[4][2], bl[4][2];
#pragma unroll
            for (int p = 0; p < 2; p++) {
                uint32_t off = (uint32_t)((wn * 32 + p * 16 + b_row) * SROW + ks * 8 + b_hk) * 4;
                uint32_t rr[4];
                ldsm4(rr, sBh + off);
                bh[2*p][0] = rr[0]; bh[2*p][1] = rr[1];
                bh[2*p+1][0] = rr[2]; bh[2*p+1][1] = rr[3];
                ldsm4(rr, sBl + off);
                bl[2*p][0] = rr[0]; bl[2*p][1] = rr[1];
                bl[2*p+1][0] = rr[2]; bl[2*p+1][1] = rr[3];
            }
#pragma unroll
            for (int mt = 0; mt < 4; mt++) {
                uint32_t off = (uint32_t)((wm * 64 + mt * 16 + a_row) * SROW + ks * 8 + a_hk) * 4;
                uint32_t ah[4], al[4];
                ldsm4(ah, sAh + off);
                ldsm4(al, sAl + off);
#pragma unroll
                for (int nt = 0; nt < 4; nt++) {
                    mma16816(c[mt][nt], ah, bh[nt]);
                    mma16816(c[mt][nt], al, bh[nt]);
                    mma16816(c[mt][nt], ah, bl[nt]);
                }
            }
        }
    }
}

// ============================================================================
// Fused QKV projection (z picks weight + epilogue)
// ============================================================================
__global__ __launch_bounds__(256, 2) void gemm_qkv()
{
    extern __shared__ __align__(16) uint32_t dsm[];
    const uint32_t smb = smem_u32(dsm);

    const int tid  = threadIdx.x;
    const int warp = tid >> 5, lane = tid & 31;
    const int g = lane >> 2, t = lane & 3;
    const int wm = warp >> 2, wn = warp & 3;
    const int m0 = blockIdx.y * 128, n0 = blockIdx.x * 128;
    const int z = blockIdx.z;
    const uint16_t* Bgh = (z == 0) ? g_wqh : ((z == 1) ? g_wkh : g_wvh);
    const uint16_t* Bgl = (z == 0) ? g_wql : ((z == 1) ? g_wkl : g_wvl);

    float c[4][4][4];
#pragma unroll
    for (int i = 0; i < 4; i++)
#pragma unroll
        for (int j = 0; j < 4; j++)
#pragma unroll
            for (int r = 0; r < 4; r++) c[i][j][r] = 0.f;

    gemm_core_bf(g_xh, g_xl, Bgh, Bgl, smb, m0, n0, tid, c);

    if (z < 2) {
        uint16_t* Hh = (z == 0) ? g_qh : g_kh;
        uint16_t* Hl = (z == 0) ? g_ql : g_kl;
        const float sc = (z == 0) ? 0.125f : 1.0f;
#pragma unroll
        for (int mt = 0; mt < 4; mt++) {
#pragma unroll
            for (int nt = 0; nt < 4; nt++) {
                int row = m0 + wm * 64 + mt * 16 + g;
                int col = n0 + wn * 32 + nt * 8 + 2 * t;
                float x0 = c[mt][nt][0] * sc, x1 = c[mt][nt][1] * sc;
                float x2 = c[mt][nt][2] * sc, x3 = c[mt][nt][3] * sc;
                uint32_t h0 = bfpack(x0, x1), h1 = bfpack(x2, x3);
                *(uint32_t*)&Hh[(long)row * DM + col]       = h0;
                *(uint32_t*)&Hl[(long)row * DM + col]       = bfpack(x0 - lo_of(h0), x1 - hi_of(h0));
                *(uint32_t*)&Hh[(long)(row + 8) * DM + col] = h1;
                *(uint32_t*)&Hl[(long)(row + 8) * DM + col] = bfpack(x2 - lo_of(h1), x3 - hi_of(h1));
            }
        }
    } else {
        // V: transpose 128x128 tile via smem, write [(b,h,dl)][token] bf16 hi/lo
        uint16_t* st = (uint16_t*)dsm;      // 128 x 136 u16 = 34816 B (< 81920)
        const int b = m0 / SEQ, s0 = m0 % SEQ;
#pragma unroll
        for (int pass = 0; pass < 2; pass++) {
            __syncthreads();
#pragma unroll
            for (int mt = 0; mt < 4; mt++)
#pragma unroll
                for (int nt = 0; nt < 4; nt++)
#pragma unroll
                    for (int r = 0; r < 4; r++) {
                        float cv = c[mt][nt][r];
                        uint16_t hv = bf1(cv);
                        uint16_t val = pass ? bf1(cv - bf1v(hv)) : hv;
                        int rowl = wm * 64 + mt * 16 + g + ((r >> 1) ? 8 : 0);
                        int coll = wn * 32 + nt * 8 + 2 * t + (r & 1);
                        st[coll * 136 + rowl] = val;
                    }
            __syncthreads();
            uint16_t* dstb = pass ? g_vtl : g_vth;
#pragma unroll
            for (int u = 0; u < 8; u++) {
                int idx = tid + u * 256;
                int dl128 = idx >> 4, ch = idx & 15;
                uint4 v = *(const uint4*)&st[dl128 * 136 + ch * 8];
                int colg = n0 + dl128;
                int hh = colg >> 6, dl = colg & 63;
                *(uint4*)&dstb[((long)((b * NH + hh) * DK + dl)) * SEQ + s0 + ch * 8] = v;
            }
        }
    }
}

// ============================================================================
// Output projection GEMM (pre-split A from flash, fp32 out)
// ============================================================================
__global__ __launch_bounds__(256, 2) void gemm_out(float* __restrict__ C)
{
    extern __shared__ __align__(16) uint32_t dsm[];
    const uint32_t smb = smem_u32(dsm);

    const int tid  = threadIdx.x;
    const int warp = tid >> 5, lane = tid & 31;
    const int g = lane >> 2, t = lane & 3;
    const int wm = warp >> 2, wn = warp & 3;
    const int m0 = blockIdx.y * 128, n0 = blockIdx.x * 128;

    float c[4][4][4];
#pragma unroll
    for (int i = 0; i < 4; i++)
#pragma unroll
        for (int j = 0; j < 4; j++)
#pragma unroll
            for (int r = 0; r < 4; r++) c[i][j][r] = 0.f;

    gemm_core_bf(g_ah, g_al, g_woh, g_wol, smb, m0, n0, tid, c);

#pragma unroll
    for (int mt = 0; mt < 4; mt++) {
#pragma unroll
        for (int nt = 0; nt < 4; nt++) {
            int row = m0 + wm * 64 + mt * 16 + g;
            int col = n0 + wn * 32 + nt * 8 + t * 2;
            *(float2*)&C[(long)row * DM + col]       = make_float2(c[mt][nt][0], c[mt][nt][1]);
            *(float2*)&C[(long)(row + 8) * DM + col] = make_float2(c[mt][nt][2], c[mt][nt][3]);
        }
    }
}

// ============================================================================
// Flash attention: pre-converted bf16 inputs, cp.async double-buffered K/V,
// LDSM fragment loads. BQ=128, BK=64. grid = (SEQ/128, NH, BATCH).
// ============================================================================
#define VS 36
#define ARR_U32 (64*VS)
#define STAGE_U32 (4*ARR_U32)
#define FL_SMEM (2*STAGE_U32*4)         // 73728 B

__global__ __launch_bounds__(256) void flash_mma()
{
    extern __shared__ __align__(16) uint32_t fsm[];
    const uint32_t smb = smem_u32(fsm);

    const int tid  = threadIdx.x;
    const int warp = tid >> 5, lane = tid & 31;
    const int g = lane >> 2, t = lane & 3;
    const int qb = blockIdx.x, h = blockIdx.y, b = blockIdx.z;
    const int q0 = qb * 128;
    const int headoff = h * DK;
    const long rowbase = (long)(b * SEQ + q0 + warp * 16);
    const long vtbase  = (long)((b * NH + h) * DK) * SEQ;
    const float NEG_INF = __int_as_float(0xff800000);

    const int f_row = ((lane >> 4) << 3) + (lane & 7);
    const int f_hk  = ((lane >> 3) & 1) * 4;

    // ---- Q fragments (already scaled + split) ----
    uint32_t qh[4][4], ql[4][4];
#pragma unroll
    for (int ks = 0; ks < 4; ks++) {
#pragma unroll
        for (int idx = 0; idx < 4; idx++) {
            int rr = (idx & 1) ? g + 8 : g;
            int d0 = ks * 16 + ((idx >> 1) ? 2 * t + 8 : 2 * t);
            long off = (rowbase + rr) * DM + headoff + d0;
            qh[ks][idx] = *(const uint32_t*)&g_qh[off];
            ql[ks][idx] = *(const uint32_t*)&g_ql[off];
        }
    }

    float m[2] = {NEG_INF, NEG_INF}, l[2] = {0.f, 0.f};
    float o[8][4];
#pragma unroll
    for (int dt = 0; dt < 8; dt++)
#pragma unroll
        for (int r = 0; r < 4; r++) o[dt][r] = 0.f;

    const int jmax = 2 * (qb + 1);

    auto prefetch = [&](int jb, int stg) {
        const int ch = tid & 7;
#pragma unroll
        for (int u = 0; u < 8; u++) {
            int arr = u >> 1;
            int r2  = ((u & 1) << 5) + (tid >> 3);
            const uint16_t* src;
            long koff = (long)(b * SEQ + jb * 64 + r2) * DM + headoff + ch * 8;
            long voff = vtbase + (long)r2 * SEQ + jb * 64 + ch * 8;
            if      (arr == 0) src = g_kh  + koff;
            else if (arr == 1) src = g_kl  + koff;
            else if (arr == 2) src = g_vth + voff;
            else               src = g_vtl + voff;
            uint32_t dst = smb + (uint32_t)(stg * STAGE_U32 + arr * ARR_U32 + r2 * VS) * 4 + ch * 16;
            CP16(dst, src);
        }
        CP_COMMIT();
    };

    prefetch(0, 0);

    for (int jb = 0; jb < jmax; jb++) {
        const int stg = jb & 1;
        CP_WAIT0();
        __syncthreads();
        if (jb + 1 < jmax) prefetch(jb + 1, stg ^ 1);

        const uint32_t sK  = smb + (uint32_t)(stg * STAGE_U32) * 4;
        const uint32_t sKl = sK + ARR_U32 * 4;
        const uint32_t sVh = sK + 2 * ARR_U32 * 4;
        const uint32_t sVl = sK + 3 * ARR_U32 * 4;

        // ---- S = Q K^T ----
        float s[8][4];
#pragma unroll
        for (int nt = 0; nt < 8; nt++)
#pragma unroll
            for (int r = 0; r < 4; r++) s[nt][r] = 0.f;
#pragma unroll
        for (int ks = 0; ks < 4; ks++) {
#pragma unroll
            for (int p = 0; p < 4; p++) {
                uint32_t off = (uint32_t)((p * 16 + f_row) * VS + ks * 8 + f_hk) * 4;
                uint32_t kh[4], kl[4];
                ldsm4(kh, sK  + off);
                ldsm4(kl, sKl + off);
                mma16816(s[2*p],   qh[ks], kh);
                mma16816(s[2*p],   ql[ks], kh);
                mma16816(s[2*p],   qh[ks], kl);
                mma16816(s[2*p+1], qh[ks], kh + 2);
                mma16816(s[2*p+1], ql[ks], kh + 2);
                mma16816(s[2*p+1], qh[ks], kl + 2);
            }
        }

        // ---- causal mask ----
        if (jb >= 2 * qb) {
#pragma unroll
            for (int nt = 0; nt < 8; nt++)
#pragma unroll
                for (int r = 0; r < 4; r++) {
                    int key = jb * 64 + nt * 8 + 2 * t + (r & 1);
                    int qr  = q0 + warp * 16 + g + ((r >> 1) ? 8 : 0);
                    if (key > qr) s[nt][r] = NEG_INF;
                }
        }

        // ---- online softmax ----
        float mx0 = NEG_INF, mx1 = NEG_INF;
#pragma unroll
        for (int nt = 0; nt < 8; nt++) {
            mx0 = fmaxf(mx0, fmaxf(s[nt][0], s[nt][1]));
            mx1 = fmaxf(mx1, fmaxf(s[nt][2], s[nt][3]));
        }
        mx0 = fmaxf(mx0, __shfl_xor_sync(0xffffffffu, mx0, 1));
        mx0 = fmaxf(mx0, __shfl_xor_sync(0xffffffffu, mx0, 2));
        mx1 = fmaxf(mx1, __shfl_xor_sync(0xffffffffu, mx1, 1));
        mx1 = fmaxf(mx1, __shfl_xor_sync(0xffffffffu, mx1, 2));
        float mn0 = fmaxf(m[0], mx0), mn1 = fmaxf(m[1], mx1);
        float al0 = __expf(m[0] - mn0), al1 = __expf(m[1] - mn1);
        m[0] = mn0; m[1] = mn1;
        float ps0 = 0.f, ps1 = 0.f;
#pragma unroll
        for (int nt = 0; nt < 8; nt++) {
            s[nt][0] = __expf(s[nt][0] - mn0); ps0 += s[nt][0];
            s[nt][1] = __expf(s[nt][1] - mn0); ps0 += s[nt][1];
            s[nt][2] = __expf(s[nt][2] - mn1); ps1 += s[nt][2];
            s[nt][3] = __expf(s[nt][3] - mn1); ps1 += s[nt][3];
        }
        ps0 += __shfl_xor_sync(0xffffffffu, ps0, 1);
        ps0 += __shfl_xor_sync(0xffffffffu, ps0, 2);
        ps1 += __shfl_xor_sync(0xffffffffu, ps1, 1);
        ps1 += __shfl_xor_sync(0xffffffffu, ps1, 2);
        l[0] = l[0] * al0 + ps0;
        l[1] = l[1] * al1 + ps1;
#pragma unroll
        for (int dt = 0; dt < 8; dt++) {
            o[dt][0] *= al0; o[dt][1] *= al0;
            o[dt][2] *= al1; o[dt][3] *= al1;
        }

        // ---- O += P V ----
#pragma unroll
        for (int kt = 0; kt < 4; kt++) {
            uint32_t ph[4], pl[4];
            ph[0] = bfpack(s[2*kt][0],   s[2*kt][1]);
            ph[1] = bfpack(s[2*kt][2],   s[2*kt][3]);
            ph[2] = bfpack(s[2*kt+1][0], s[2*kt+1][1]);
            ph[3] = bfpack(s[2*kt+1][2], s[2*kt+1][3]);
            pl[0] = bfpack(s[2*kt][0]   - lo_of(ph[0]), s[2*kt][1]   - hi_of(ph[0]));
            pl[1] = bfpack(s[2*kt][2]   - lo_of(ph[1]), s[2*kt][3]   - hi_of(ph[1]));
            pl[2] = bfpack(s[2*kt+1][0] - lo_of(ph[2]), s[2*kt+1][1] - hi_of(ph[2]));
            pl[3] = bfpack(s[2*kt+1][2] - lo_of(ph[3]), s[2*kt+1][3] - hi_of(ph[3]));
#pragma unroll
            for (int p = 0; p < 4; p++) {
                uint32_t off = (uint32_t)((p * 16 + f_row) * VS + kt * 8 + f_hk) * 4;
                uint32_t vh[4], vl[4];
                ldsm4(vh, sVh + off);
                ldsm4(vl, sVl + off);
                mma16816(o[2*p],   ph, vh);
                mma16816(o[2*p],   pl, vh);
                mma16816(o[2*p],   ph, vl);
                mma16816(o[2*p+1], ph, vh + 2);
                mma16816(o[2*p+1], pl, vh + 2);
                mma16816(o[2*p+1], ph, vl + 2);
            }
        }
    }

    // ---- epilogue: write bf16 hi/lo for the output projection ----
    float inv0 = 1.f / l[0], inv1 = 1.f / l[1];
#pragma unroll
    for (int dt = 0; dt < 8; dt++) {
        int col = headoff + dt * 8 + 2 * t;
        float a0 = o[dt][0] * inv0, a1 = o[dt][1] * inv0;
        float a2 = o[dt][2] * inv1, a3 = o[dt][3] * inv1;
        uint32_t h0 = bfpack(a0, a1), h1 = bfpack(a2, a3);
        *(uint32_t*)&g_ah[(rowbase + g) * DM + col]     = h0;
        *(uint32_t*)&g_al[(rowbase + g) * DM + col]     = bfpack(a0 - lo_of(h0), a1 - hi_of(h0));
        *(uint32_t*)&g_ah[(rowbase + g + 8) * DM + col] = h1;
        *(uint32_t*)&g_al[(rowbase + g + 8) * DM + col] = bfpack(a2 - lo_of(h1), a3 - hi_of(h1));
    }
}

// ---------------------------------------------------------------------------
extern "C" void kernel_launch(void* const* d_in, const int* in_sizes, int n_in,
                              void* d_out, int out_size)
{
    const float* x  = (const float*)d_in[0];
    const float* wq = (const float*)d_in[1];
    const float* wk = (const float*)d_in[2];
    const float* wv = (const float*)d_in[3];
    const float* wo = (const float*)d_in[4];
    float* out = (float*)d_out;

    uint16_t *xh, *xl, *wqh, *wql, *wkh, *wkl, *wvh, *wvl, *woh, *wol;
    cudaGetSymbolAddress((void**)&xh,  g_xh);  cudaGetSymbolAddress((void**)&xl,  g_xl);
    cudaGetSymbolAddress((void**)&wqh, g_wqh); cudaGetSymbolAddress((void**)&wql, g_wql);
    cudaGetSymbolAddress((void**)&wkh, g_wkh); cudaGetSymbolAddress((void**)&wkl, g_wkl);
    cudaGetSymbolAddress((void**)&wvh, g_wvh); cudaGetSymbolAddress((void**)&wvl, g_wvl);
    cudaGetSymbolAddress((void**)&woh, g_woh); cudaGetSymbolAddress((void**)&wol, g_wol);

    cudaFuncSetAttribute(flash_mma, cudaFuncAttributeMaxDynamicSharedMemorySize, FL_SMEM);
    cudaFuncSetAttribute(gemm_qkv,  cudaFuncAttributeMaxDynamicSharedMemorySize, G_SMEM);
    cudaFuncSetAttribute(gemm_out,  cudaFuncAttributeMaxDynamicSharedMemorySize, G_SMEM);

    const int nx4 = MROWS * DM / 4, nw4 = DM * DM / 4;
    conv_split<<<(nx4 + 255) / 256, 256>>>(x,  xh,  xl,  nx4);
    conv_split<<<(nw4 + 255) / 256, 256>>>(wq, wqh, wql, nw4);
    conv_split<<<(nw4 + 255) / 256, 256>>>(wk, wkh, wkl, nw4);
    conv_split<<<(nw4 + 255) / 256, 256>>>(wv, wvh, wvl, nw4);
    conv_split<<<(nw4 + 255) / 256, 256>>>(wo, woh, wol, nw4);

    gemm_qkv<<<dim3(DM / 128, MROWS / 128, 3), 256, G_SMEM>>>();
    flash_mma<<<dim3(SEQ / 128, NH, BATCH), 256, FL_SMEM>>>();
    gemm_out<<<dim3(DM / 128, MROWS / 128), 256, G_SMEM>>>(out);
}

// round 12
// speedup vs baseline: 1.0424x; 1.0424x over previous
#include <cuda_runtime.h>
#include <cstdint>

#define BATCH 2
#define SEQ   2048
#define DM    768
#define NH    12
#define DK    64
#define MROWS (BATCH*SEQ)

// Scratch (allocation-free rule: __device__ globals)
__device__ uint16_t g_xh[MROWS*DM],  g_xl[MROWS*DM];
__device__ uint16_t g_qh[MROWS*DM],  g_ql[MROWS*DM];
__device__ uint16_t g_kh[MROWS*DM],  g_kl[MROWS*DM];
__device__ uint16_t g_vth[MROWS*DM], g_vtl[MROWS*DM];
__device__ uint16_t g_ah[MROWS*DM],  g_al[MROWS*DM];
__device__ uint16_t g_wqh[DM*DM], g_wql[DM*DM];
__device__ uint16_t g_wkh[DM*DM], g_wkl[DM*DM];
__device__ uint16_t g_wvh[DM*DM], g_wvl[DM*DM];
__device__ uint16_t g_woh[DM*DM], g_wol[DM*DM];

// ============================================================================
// helpers
// ============================================================================
__device__ __forceinline__ uint32_t smem_u32(const void* p) {
    uint32_t a;
    asm("{ .reg .u64 t; cvta.to.shared.u64 t, %1; cvt.u32.u64 %0, t; }" : "=r"(a) : "l"(p));
    return a;
}
__device__ __forceinline__ uint32_t bfpack(float x, float y) {
    uint32_t r;
    asm("cvt.rn.bf16x2.f32 %0, %1, %2;" : "=r"(r) : "f"(y), "f"(x));
    return r;
}
__device__ __forceinline__ float lo_of(uint32_t p)  { return __uint_as_float(p << 16); }
__device__ __forceinline__ float hi_of(uint32_t p)  { return __uint_as_float(p & 0xffff0000u); }
__device__ __forceinline__ uint16_t bf1(float x) {
    uint16_t u; asm("cvt.rn.bf16.f32 %0, %1;" : "=h"(u) : "f"(x)); return u;
}
__device__ __forceinline__ float bf1v(uint16_t u) { return __uint_as_float(((uint32_t)u) << 16); }

__device__ __forceinline__ void mma16816(float* c, const uint32_t* a, const uint32_t* b) {
    asm volatile(
        "mma.sync.aligned.m16n8k16.row.col.f32.bf16.bf16.f32 "
        "{%0,%1,%2,%3}, {%4,%5,%6,%7}, {%8,%9}, {%0,%1,%2,%3};"
        : "+f"(c[0]), "+f"(c[1]), "+f"(c[2]), "+f"(c[3])
        : "r"(a[0]), "r"(a[1]), "r"(a[2]), "r"(a[3]), "r"(b[0]), "r"(b[1]));
}
__device__ __forceinline__ void ldsm4(uint32_t* r, uint32_t addr) {
    asm volatile("ldmatrix.sync.aligned.m8n8.x4.shared.b16 {%0,%1,%2,%3}, [%4];"
        : "=r"(r[0]), "=r"(r[1]), "=r"(r[2]), "=r"(r[3]) : "r"(addr));
}
#define CP16(dst, src) asm volatile("cp.async.ca.shared.global [%0], [%1], 16;" :: "r"(dst), "l"(src))
#define CP_COMMIT()    asm volatile("cp.async.commit_group;" ::: "memory")
#define CP_WAIT0()     asm volatile("cp.async.wait_group 0;" ::: "memory")

// ============================================================================
// Single fused fp32 -> bf16 hi/lo split over x + 4 weights
// ============================================================================
#define NX4 (MROWS*DM/4)
#define NW4 (DM*DM/4)

__global__ __launch_bounds__(256) void conv_all(const float* __restrict__ x,
                                                const float* __restrict__ wq,
                                                const float* __restrict__ wk,
                                                const float* __restrict__ wv,
                                                const float* __restrict__ wo)
{
    long i = (long)blockIdx.x * blockDim.x + threadIdx.x;
    const float* src; uint16_t *dh, *dl; long j;
    if (i < NX4)                 { src = x;  dh = g_xh;  dl = g_xl;  j = i; }
    else if (i < NX4 + NW4)      { src = wq; dh = g_wqh; dl = g_wql; j = i - NX4; }
    else if (i < NX4 + 2*NW4)    { src = wk; dh = g_wkh; dl = g_wkl; j = i - NX4 - NW4; }
    else if (i < NX4 + 3*NW4)    { src = wv; dh = g_wvh; dl = g_wvl; j = i - NX4 - 2*NW4; }
    else if (i < NX4 + 4*NW4)    { src = wo; dh = g_woh; dl = g_wol; j = i - NX4 - 3*NW4; }
    else return;
    float4 v = ((const float4*)src)[j];
    uint32_t h0 = bfpack(v.x, v.y), h1 = bfpack(v.z, v.w);
    ((uint2*)dh)[j] = make_uint2(h0, h1);
    ((uint2*)dl)[j] = make_uint2(bfpack(v.x - lo_of(h0), v.y - hi_of(h0)),
                                 bfpack(v.z - lo_of(h1), v.w - hi_of(h1)));
}

// ============================================================================
// GEMM core: cp.async double-buffered, LDSM, term-major mma (chain distance 4)
// ============================================================================
#define SROW 20
#define GST_U32 (128*SROW)
#define GSTAGE_U32 (4*GST_U32)
#define G_SMEM (2*GSTAGE_U32*4)        // 81920 B

__device__ __forceinline__ void gemm_core_bf(const uint16_t* __restrict__ Agh,
                                             const uint16_t* __restrict__ Agl,
                                             const uint16_t* __restrict__ Bgh,
                                             const uint16_t* __restrict__ Bgl,
                                             uint32_t smb, int m0, int n0,
                                             int tid, float c[4][4][4])
{
    const int warp = tid >> 5, lane = tid & 31;
    const int wm = warp >> 2, wn = warp & 3;
    const int a_row = lane & 15,                  a_hk = (lane >> 4) * 4;
    const int b_row = ((lane >> 4) << 3) + (lane & 7), b_hk = ((lane >> 3) & 1) * 4;

    auto pre = [&](int kc, int stg) {
#pragma unroll
        for (int u = 0; u < 8; u++) {
            int idx = tid + u * 256;
            int arr = idx >> 9, row = (idx >> 2) & 127, ch = idx & 3;
            const uint16_t* src;
            if      (arr == 0) src = Agh + (long)(m0 + row) * DM + kc * 32 + ch * 8;
            else if (arr == 1) src = Agl + (long)(m0 + row) * DM + kc * 32 + ch * 8;
            else if (arr == 2) src = Bgh + (long)(n0 + row) * DM + kc * 32 + ch * 8;
            else               src = Bgl + (long)(n0 + row) * DM + kc * 32 + ch * 8;
            uint32_t dst = smb + (uint32_t)((stg * 4 + arr) * GST_U32 + row * SROW + ch * 4) * 4;
            CP16(dst, src);
        }
        CP_COMMIT();
    };

    pre(0, 0);

    for (int kc = 0; kc < DM / 32; kc++) {
        const int stg = kc & 1;
        CP_WAIT0();
        __syncthreads();
        if (kc + 1 < DM / 32) pre(kc + 1, stg ^ 1);

        const uint32_t sAh = smb + (uint32_t)(stg * GSTAGE_U32) * 4;
        const uint32_t sAl = sAh + GST_U32 * 4;
        const uint32_t sBh = sAh + 2 * GST_U32 * 4;
        const uint32_t sBl = sAh + 3 * GST_U32 * 4;

#pragma unroll
        for (int ks = 0; ks < 2; ks++) {
            uint32_t bh[4][2], bl[4][2];
#pragma unroll
            for (int p = 0; p < 2; p++) {
                uint32_t off = (uint32_t)((wn * 32 + p * 16 + b_row) * SROW + ks * 8 + b_hk) * 4;
                uint32_t rr[4];
                ldsm4(rr, sBh + off);
                bh[2*p][0] = rr[0]; bh[2*p][1] = rr[1];
                bh[2*p+1][0] = rr[2]; bh[2*p+1][1] = rr[3];
                ldsm4(rr, sBl + off);
                bl[2*p][0] = rr[0]; bl[2*p][1] = rr[1];
                bl[2*p+1][0] = rr[2]; bl[2*p+1][1] = rr[3];
            }
#pragma unroll
            for (int mt = 0; mt < 4; mt++) {
                uint32_t off = (uint32_t)((wm * 64 + mt * 16 + a_row) * SROW + ks * 8 + a_hk) * 4;
                uint32_t ah[4], al[4];
                ldsm4(ah, sAh + off);
                ldsm4(al, sAl + off);
                // term-major: same-accumulator mmas are 4 issues apart
#pragma unroll
                for (int nt = 0; nt < 4; nt++) mma16816(c[mt][nt], ah, bh[nt]);
#pragma unroll
                for (int nt = 0; nt < 4; nt++) mma16816(c[mt][nt], al, bh[nt]);
#pragma unroll
                for (int nt = 0; nt < 4; nt++) mma16816(c[mt][nt], ah, bl[nt]);
            }
        }
    }
}

// ============================================================================
// Fused QKV projection
// ============================================================================
__global__ __launch_bounds__(256, 2) void gemm_qkv()
{
    extern __shared__ __align__(16) uint32_t dsm[];
    const uint32_t smb = smem_u32(dsm);

    const int tid  = threadIdx.x;
    const int warp = tid >> 5, lane = tid & 31;
    const int g = lane >> 2, t = lane & 3;
    const int wm = warp >> 2, wn = warp & 3;
    const int m0 = blockIdx.y * 128, n0 = blockIdx.x * 128;
    const int z = blockIdx.z;
    const uint16_t* Bgh = (z == 0) ? g_wqh : ((z == 1) ? g_wkh : g_wvh);
    const uint16_t* Bgl = (z == 0) ? g_wql : ((z == 1) ? g_wkl : g_wvl);

    float c[4][4][4];
#pragma unroll
    for (int i = 0; i < 4; i++)
#pragma unroll
        for (int j = 0; j < 4; j++)
#pragma unroll
            for (int r = 0; r < 4; r++) c[i][j][r] = 0.f;

    gemm_core_bf(g_xh, g_xl, Bgh, Bgl, smb, m0, n0, tid, c);

    if (z < 2) {
        uint16_t* Hh = (z == 0) ? g_qh : g_kh;
        uint16_t* Hl = (z == 0) ? g_ql : g_kl;
        const float sc = (z == 0) ? 0.125f : 1.0f;
#pragma unroll
        for (int mt = 0; mt < 4; mt++) {
#pragma unroll
            for (int nt = 0; nt < 4; nt++) {
                int row = m0 + wm * 64 + mt * 16 + g;
                int col = n0 + wn * 32 + nt * 8 + 2 * t;
                float x0 = c[mt][nt][0] * sc, x1 = c[mt][nt][1] * sc;
                float x2 = c[mt][nt][2] * sc, x3 = c[mt][nt][3] * sc;
                uint32_t h0 = bfpack(x0, x1), h1 = bfpack(x2, x3);
                *(uint32_t*)&Hh[(long)row * DM + col]       = h0;
                *(uint32_t*)&Hl[(long)row * DM + col]       = bfpack(x0 - lo_of(h0), x1 - hi_of(h0));
                *(uint32_t*)&Hh[(long)(row + 8) * DM + col] = h1;
                *(uint32_t*)&Hl[(long)(row + 8) * DM + col] = bfpack(x2 - lo_of(h1), x3 - hi_of(h1));
            }
        }
    } else {
        uint16_t* st = (uint16_t*)dsm;
        const int b = m0 / SEQ, s0 = m0 % SEQ;
#pragma unroll
        for (int pass = 0; pass < 2; pass++) {
            __syncthreads();
#pragma unroll
            for (int mt = 0; mt < 4; mt++)
#pragma unroll
                for (int nt = 0; nt < 4; nt++)
#pragma unroll
                    for (int r = 0; r < 4; r++) {
                        float cv = c[mt][nt][r];
                        uint16_t hv = bf1(cv);
                        uint16_t val = pass ? bf1(cv - bf1v(hv)) : hv;
                        int rowl = wm * 64 + mt * 16 + g + ((r >> 1) ? 8 : 0);
                        int coll = wn * 32 + nt * 8 + 2 * t + (r & 1);
                        st[coll * 136 + rowl] = val;
                    }
            __syncthreads();
            uint16_t* dstb = pass ? g_vtl : g_vth;
#pragma unroll
            for (int u = 0; u < 8; u++) {
                int idx = tid + u * 256;
                int dl128 = idx >> 4, ch = idx & 15;
                uint4 v = *(const uint4*)&st[dl128 * 136 + ch * 8];
                int colg = n0 + dl128;
                int hh = colg >> 6, dl = colg & 63;
                *(uint4*)&dstb[((long)((b * NH + hh) * DK + dl)) * SEQ + s0 + ch * 8] = v;
            }
        }
    }
}

// ============================================================================
// Output projection GEMM
// ============================================================================
__global__ __launch_bounds__(256, 2) void gemm_out(float* __restrict__ C)
{
    extern __shared__ __align__(16) uint32_t dsm[];
    const uint32_t smb = smem_u32(dsm);

    const int tid  = threadIdx.x;
    const int warp = tid >> 5, lane = tid & 31;
    const int g = lane >> 2, t = lane & 3;
    const int wm = warp >> 2, wn = warp & 3;
    const int m0 = blockIdx.y * 128, n0 = blockIdx.x * 128;

    float c[4][4][4];
#pragma unroll
    for (int i = 0; i < 4; i++)
#pragma unroll
        for (int j = 0; j < 4; j++)
#pragma unroll
            for (int r = 0; r < 4; r++) c[i][j][r] = 0.f;

    gemm_core_bf(g_ah, g_al, g_woh, g_wol, smb, m0, n0, tid, c);

#pragma unroll
    for (int mt = 0; mt < 4; mt++) {
#pragma unroll
        for (int nt = 0; nt < 4; nt++) {
            int row = m0 + wm * 64 + mt * 16 + g;
            int col = n0 + wn * 32 + nt * 8 + t * 2;
            *(float2*)&C[(long)row * DM + col]       = make_float2(c[mt][nt][0], c[mt][nt][1]);
            *(float2*)&C[(long)(row + 8) * DM + col] = make_float2(c[mt][nt][2], c[mt][nt][3]);
        }
    }
}

// ============================================================================
// Flash attention: longest-qb-first, prefetch before Q loads, pair-interleaved mma
// ============================================================================
#define VS 36
#define ARR_U32 (64*VS)
#define STAGE_U32 (4*ARR_U32)
#define FL_SMEM (2*STAGE_U32*4)         // 73728 B

__global__ __launch_bounds__(256) void flash_mma()
{
    extern __shared__ __align__(16) uint32_t fsm[];
    const uint32_t smb = smem_u32(fsm);

    const int tid  = threadIdx.x;
    const int warp = tid >> 5, lane = tid & 31;
    const int g = lane >> 2, t = lane & 3;
    const int qb = gridDim.x - 1 - blockIdx.x;    // longest CTAs first
    const int h = blockIdx.y, b = blockIdx.z;
    const int q0 = qb * 128;
    const int headoff = h * DK;
    const long rowbase = (long)(b * SEQ + q0 + warp * 16);
    const long vtbase  = (long)((b * NH + h) * DK) * SEQ;
    const float NEG_INF = __int_as_float(0xff800000);

    const int f_row = ((lane >> 4) << 3) + (lane & 7);
    const int f_hk  = ((lane >> 3) & 1) * 4;

    const int jmax = 2 * (qb + 1);

    auto prefetch = [&](int jb, int stg) {
        const int ch = tid & 7;
#pragma unroll
        for (int u = 0; u < 8; u++) {
            int arr = u >> 1;
            int r2  = ((u & 1) << 5) + (tid >> 3);
            const uint16_t* src;
            long koff = (long)(b * SEQ + jb * 64 + r2) * DM + headoff + ch * 8;
            long voff = vtbase + (long)r2 * SEQ + jb * 64 + ch * 8;
            if      (arr == 0) src = g_kh  + koff;
            else if (arr == 1) src = g_kl  + koff;
            else if (arr == 2) src = g_vth + voff;
            else               src = g_vtl + voff;
            uint32_t dst = smb + (uint32_t)(stg * STAGE_U32 + arr * ARR_U32 + r2 * VS) * 4 + ch * 16;
            CP16(dst, src);
        }
        CP_COMMIT();
    };

    prefetch(0, 0);   // overlap with Q fragment LDGs below

    // ---- Q fragments (already scaled + split) ----
    uint32_t qh[4][4], ql[4][4];
#pragma unroll
    for (int ks = 0; ks < 4; ks++) {
#pragma unroll
        for (int idx = 0; idx < 4; idx++) {
            int rr = (idx & 1) ? g + 8 : g;
            int d0 = ks * 16 + ((idx >> 1) ? 2 * t + 8 : 2 * t);
            long off = (rowbase + rr) * DM + headoff + d0;
            qh[ks][idx] = *(const uint32_t*)&g_qh[off];
            ql[ks][idx] = *(const uint32_t*)&g_ql[off];
        }
    }

    float m[2] = {NEG_INF, NEG_INF}, l[2] = {0.f, 0.f};
    float o[8][4];
#pragma unroll
    for (int dt = 0; dt < 8; dt++)
#pragma unroll
        for (int r = 0; r < 4; r++) o[dt][r] = 0.f;

    for (int jb = 0; jb < jmax; jb++) {
        const int stg = jb & 1;
        CP_WAIT0();
        __syncthreads();
        if (jb + 1 < jmax) prefetch(jb + 1, stg ^ 1);

        const uint32_t sK  = smb + (uint32_t)(stg * STAGE_U32) * 4;
        const uint32_t sKl = sK + ARR_U32 * 4;
        const uint32_t sVh = sK + 2 * ARR_U32 * 4;
        const uint32_t sVl = sK + 3 * ARR_U32 * 4;

        // ---- S = Q K^T (pair-interleaved: same-acc distance 4) ----
        float s[8][4];
#pragma unroll
        for (int nt = 0; nt < 8; nt++)
#pragma unroll
            for (int r = 0; r < 4; r++) s[nt][r] = 0.f;
#pragma unroll
        for (int ks = 0; ks < 4; ks++) {
#pragma unroll
            for (int pp = 0; pp < 2; pp++) {
                uint32_t off0 = (uint32_t)(((2*pp)   * 16 + f_row) * VS + ks * 8 + f_hk) * 4;
                uint32_t off1 = (uint32_t)(((2*pp+1) * 16 + f_row) * VS + ks * 8 + f_hk) * 4;
                uint32_t kh0[4], kl0[4], kh1[4], kl1[4];
                ldsm4(kh0, sK  + off0);
                ldsm4(kl0, sKl + off0);
                ldsm4(kh1, sK  + off1);
                ldsm4(kl1, sKl + off1);
                float* s0 = s[4*pp]; float* s1 = s[4*pp+1];
                float* s2 = s[4*pp+2]; float* s3 = s[4*pp+3];
                mma16816(s0, qh[ks], kh0); mma16816(s1, qh[ks], kh0 + 2);
                mma16816(s2, qh[ks], kh1); mma16816(s3, qh[ks], kh1 + 2);
                mma16816(s0, ql[ks], kh0); mma16816(s1, ql[ks], kh0 + 2);
                mma16816(s2, ql[ks], kh1); mma16816(s3, ql[ks], kh1 + 2);
                mma16816(s0, qh[ks], kl0); mma16816(s1, qh[ks], kl0 + 2);
                mma16816(s2, qh[ks], kl1); mma16816(s3, qh[ks], kl1 + 2);
            }
        }

        // ---- causal mask ----
        if (jb >= 2 * qb) {
#pragma unroll
            for (int nt = 0; nt < 8; nt++)
#pragma unroll
                for (int r = 0; r < 4; r++) {
                    int key = jb * 64 + nt * 8 + 2 * t + (r & 1);
                    int qr  = q0 + warp * 16 + g + ((r >> 1) ? 8 : 0);
                    if (key > qr) s[nt][r] = NEG_INF;
                }
        }

        // ---- online softmax ----
        float mx0 = NEG_INF, mx1 = NEG_INF;
#pragma unroll
        for (int nt = 0; nt < 8; nt++) {
            mx0 = fmaxf(mx0, fmaxf(s[nt][0], s[nt][1]));
            mx1 = fmaxf(mx1, fmaxf(s[nt][2], s[nt][3]));
        }
        mx0 = fmaxf(mx0, __shfl_xor_sync(0xffffffffu, mx0, 1));
        mx0 = fmaxf(mx0, __shfl_xor_sync(0xffffffffu, mx0, 2));
        mx1 = fmaxf(mx1, __shfl_xor_sync(0xffffffffu, mx1, 1));
        mx1 = fmaxf(mx1, __shfl_xor_sync(0xffffffffu, mx1, 2));
        float mn0 = fmaxf(m[0], mx0), mn1 = fmaxf(m[1], mx1);
        float al0 = __expf(m[0] - mn0), al1 = __expf(m[1] - mn1);
        m[0] = mn0; m[1] = mn1;
        float ps0 = 0.f, ps1 = 0.f;
#pragma unroll
        for (int nt = 0; nt < 8; nt++) {
            s[nt][0] = __expf(s[nt][0] - mn0); ps0 += s[nt][0];
            s[nt][1] = __expf(s[nt][1] - mn0); ps0 += s[nt][1];
            s[nt][2] = __expf(s[nt][2] - mn1); ps1 += s[nt][2];
            s[nt][3] = __expf(s[nt][3] - mn1); ps1 += s[nt][3];
        }
        ps0 += __shfl_xor_sync(0xffffffffu, ps0, 1);
        ps0 += __shfl_xor_sync(0xffffffffu, ps0, 2);
        ps1 += __shfl_xor_sync(0xffffffffu, ps1, 1);
        ps1 += __shfl_xor_sync(0xffffffffu, ps1, 2);
        l[0] = l[0] * al0 + ps0;
        l[1] = l[1] * al1 + ps1;
#pragma unroll
        for (int dt = 0; dt < 8; dt++) {
            o[dt][0] *= al0; o[dt][1] *= al0;
            o[dt][2] *= al1; o[dt][3] *= al1;
        }

        // ---- O += P V (pair-interleaved) ----
#pragma unroll
        for (int kt = 0; kt < 4; kt++) {
            uint32_t ph[4], pl[4];
            ph[0] = bfpack(s[2*kt][0],   s[2*kt][1]);
            ph[1] = bfpack(s[2*kt][2],   s[2*kt][3]);
            ph[2] = bfpack(s[2*kt+1][0], s[2*kt+1][1]);
            ph[3] = bfpack(s[2*kt+1][2], s[2*kt+1][3]);
            pl[0] = bfpack(s[2*kt][0]   - lo_of(ph[0]), s[2*kt][1]   - hi_of(ph[0]));
            pl[1] = bfpack(s[2*kt][2]   - lo_of(ph[1]), s[2*kt][3]   - hi_of(ph[1]));
            pl[2] = bfpack(s[2*kt+1][0] - lo_of(ph[2]), s[2*kt+1][1] - hi_of(ph[2]));
            pl[3] = bfpack(s[2*kt+1][2] - lo_of(ph[3]), s[2*kt+1][3] - hi_of(ph[3]));
#pragma unroll
            for (int pp = 0; pp < 2; pp++) {
                uint32_t off0 = (uint32_t)(((2*pp)   * 16 + f_row) * VS + kt * 8 + f_hk) * 4;
                uint32_t off1 = (uint32_t)(((2*pp+1) * 16 + f_row) * VS + kt * 8 + f_hk) * 4;
                uint32_t vh0[4], vl0[4], vh1[4], vl1[4];
                ldsm4(vh0, sVh + off0);
                ldsm4(vl0, sVl + off0);
                ldsm4(vh1, sVh + off1);
                ldsm4(vl1, sVl + off1);
                float* o0 = o[4*pp]; float* o1 = o[4*pp+1];
                float* o2 = o[4*pp+2]; float* o3 = o[4*pp+3];
                mma16816(o0, ph, vh0); mma16816(o1, ph, vh0 + 2);
                mma16816(o2, ph, vh1); mma16816(o3, ph, vh1 + 2);
                mma16816(o0, pl, vh0); mma16816(o1, pl, vh0 + 2);
                mma16816(o2, pl, vh1); mma16816(o3, pl, vh1 + 2);
                mma16816(o0, ph, vl0); mma16816(o1, ph, vl0 + 2);
                mma16816(o2, ph, vl1); mma16816(o3, ph, vl1 + 2);
            }
        }
    }

    // ---- epilogue: write bf16 hi/lo for the output projection ----
    float inv0 = 1.f / l[0], inv1 = 1.f / l[1];
#pragma unroll
    for (int dt = 0; dt < 8; dt++) {
        int col = headoff + dt * 8 + 2 * t;
        float a0 = o[dt][0] * inv0, a1 = o[dt][1] * inv0;
        float a2 = o[dt][2] * inv1, a3 = o[dt][3] * inv1;
        uint32_t h0 = bfpack(a0, a1), h1 = bfpack(a2, a3);
        *(uint32_t*)&g_ah[(rowbase + g) * DM + col]     = h0;
        *(uint32_t*)&g_al[(rowbase + g) * DM + col]     = bfpack(a0 - lo_of(h0), a1 - hi_of(h0));
        *(uint32_t*)&g_ah[(rowbase + g + 8) * DM + col] = h1;
        *(uint32_t*)&g_al[(rowbase + g + 8) * DM + col] = bfpack(a2 - lo_of(h1), a3 - hi_of(h1));
    }
}

// ---------------------------------------------------------------------------
extern "C" void kernel_launch(void* const* d_in, const int* in_sizes, int n_in,
                              void* d_out, int out_size)
{
    const float* x  = (const float*)d_in[0];
    const float* wq = (const float*)d_in[1];
    const float* wk = (const float*)d_in[2];
    const float* wv = (const float*)d_in[3];
    const float* wo = (const float*)d_in[4];
    float* out = (float*)d_out;

    cudaFuncSetAttribute(flash_mma, cudaFuncAttributeMaxDynamicSharedMemorySize, FL_SMEM);
    cudaFuncSetAttribute(gemm_qkv,  cudaFuncAttributeMaxDynamicSharedMemorySize, G_SMEM);
    cudaFuncSetAttribute(gemm_out,  cudaFuncAttributeMaxDynamicSharedMemorySize, G_SMEM);

    const long ntot = NX4 + 4L * NW4;
    conv_all<<<(int)((ntot + 255) / 256), 256>>>(x, wq, wk, wv, wo);

    gemm_qkv<<<dim3(DM / 128, MROWS / 128, 3), 256, G_SMEM>>>();
    flash_mma<<<dim3(SEQ / 128, NH, BATCH), 256, FL_SMEM>>>();
    gemm_out<<<dim3(DM / 128, MROWS / 128), 256, G_SMEM>>>(out);
}